// round 8
// baseline (speedup 1.0000x reference)
#include <cuda_runtime.h>
#include <cuda_fp16.h>
#include <mma.h>

using namespace nvcuda;

// Problem dims
#define SQ 8192
#define DD 2048
#define HH 2048
#define H3 6144

// GRU persistent kernel config
#define NB  128      // blocks (all co-resident, 1 per SM)
#define TPB 512      // 16 warps; warp w owns k-slice [w*128, w*128+128)

// GEMM config
#define BM 128
#define BN 128
#define BK 32
#define LDT 48
#define NT (DD / BK)

// -------- device scratch --------
__device__ __half g_xh[(size_t)SQ * DD];    // x fp16
__device__ __half g_wih[(size_t)H3 * DD];   // W_ih fp16
__device__ float  g_xi[(size_t)SQ * H3];    // xi fp32
__device__ __half g_h[2][HH];               // double-buffered hidden state
__device__ unsigned g_sync;                 // grid-sync counter

// -------- init (counter must be zero every launch/replay) --------
__global__ void k_init() { g_sync = 0u; }

// -------- fp32 -> fp16 conversions --------
__global__ void k_cvt_x(const float2* __restrict__ src) {
    __half2* dst = (__half2*)g_xh;
    const int n = SQ * DD / 2;
    for (int i = blockIdx.x * blockDim.x + threadIdx.x; i < n; i += gridDim.x * blockDim.x)
        dst[i] = __float22half2_rn(src[i]);
}
__global__ void k_cvt_wih(const float2* __restrict__ src) {
    __half2* dst = (__half2*)g_wih;
    const int n = H3 * DD / 2;
    for (int i = blockIdx.x * blockDim.x + threadIdx.x; i < n; i += gridDim.x * blockDim.x)
        dst[i] = __float22half2_rn(src[i]);
}

// -------- xi GEMM (proven in R3) --------
__global__ __launch_bounds__(256)
void k_gemm() {
    extern __shared__ __half tsm[];
    __half* As = tsm;
    __half* Bs = tsm + 2 * BM * LDT;

    const int tid = threadIdx.x;
    const int bm = blockIdx.y * BM;
    const int bn = blockIdx.x * BN;
    const int warp = tid >> 5;
    const int wm = (warp >> 1) * 32;
    const int wn = (warp & 1) * 64;

    wmma::fragment<wmma::accumulator, 16, 16, 16, float> acc[2][4];
#pragma unroll
    for (int i = 0; i < 2; i++)
#pragma unroll
        for (int j = 0; j < 4; j++) wmma::fill_fragment(acc[i][j], 0.0f);

    const int r0 = tid >> 2;
    const int c0 = (tid & 3) * 8;

    const __half* A = g_xh + (size_t)(bm + r0) * DD + c0;
    const __half* B = g_wih + (size_t)(bn + r0) * DD + c0;

    uint4 pa0, pa1, pb0, pb1;
    pa0 = *(const uint4*)(A);
    pa1 = *(const uint4*)(A + (size_t)64 * DD);
    pb0 = *(const uint4*)(B);
    pb1 = *(const uint4*)(B + (size_t)64 * DD);
    *(uint4*)&As[(0 * BM + r0) * LDT + c0]      = pa0;
    *(uint4*)&As[(0 * BM + r0 + 64) * LDT + c0] = pa1;
    *(uint4*)&Bs[(0 * BN + r0) * LDT + c0]      = pb0;
    *(uint4*)&Bs[(0 * BN + r0 + 64) * LDT + c0] = pb1;
    __syncthreads();

    for (int kt = 0; kt < NT; ++kt) {
        const int cur = kt & 1, nxt = cur ^ 1;
        if (kt + 1 < NT) {
            const int k0 = (kt + 1) * BK;
            pa0 = *(const uint4*)(A + k0);
            pa1 = *(const uint4*)(A + k0 + (size_t)64 * DD);
            pb0 = *(const uint4*)(B + k0);
            pb1 = *(const uint4*)(B + k0 + (size_t)64 * DD);
        }
#pragma unroll
        for (int kk = 0; kk < BK; kk += 16) {
            wmma::fragment<wmma::matrix_a, 16, 16, 16, __half, wmma::row_major> af[2];
            wmma::fragment<wmma::matrix_b, 16, 16, 16, __half, wmma::col_major> bf[4];
#pragma unroll
            for (int i = 0; i < 2; i++)
                wmma::load_matrix_sync(af[i], &As[(cur * BM + wm + i * 16) * LDT + kk], LDT);
#pragma unroll
            for (int j = 0; j < 4; j++)
                wmma::load_matrix_sync(bf[j], &Bs[(cur * BN + wn + j * 16) * LDT + kk], LDT);
#pragma unroll
            for (int i = 0; i < 2; i++)
#pragma unroll
                for (int j = 0; j < 4; j++)
                    wmma::mma_sync(acc[i][j], af[i], bf[j], acc[i][j]);
        }
        if (kt + 1 < NT) {
            *(uint4*)&As[(nxt * BM + r0) * LDT + c0]      = pa0;
            *(uint4*)&As[(nxt * BM + r0 + 64) * LDT + c0] = pa1;
            *(uint4*)&Bs[(nxt * BN + r0) * LDT + c0]      = pb0;
            *(uint4*)&Bs[(nxt * BN + r0 + 64) * LDT + c0] = pb1;
        }
        __syncthreads();
    }
#pragma unroll
    for (int i = 0; i < 2; i++)
#pragma unroll
        for (int j = 0; j < 4; j++)
            wmma::store_matrix_sync(&g_xi[(size_t)(bm + wm + i * 16) * H3 + bn + wn + j * 16],
                                    acc[i][j], H3, wmma::mem_row_major);
}

// -------- persistent GRU recurrence --------
// R3-proven sync/publish infrastructure + register-stationary m16n8k8 HMMA GEMV.
// Block b owns units j0..j0+15. Warp w owns k-slice [w*128, w*128+128).
// A-frag (canonical 2-reg): a0 = W row j0+gid, a1 = row j0+gid+8, k = 2*tig+{0,1}.
// B-frag: h replicated across all 8 columns (every lane loads h[k] for its tig).
__global__ __launch_bounds__(TPB, 1)
void k_gru(const float* __restrict__ Whh, const float* __restrict__ bih,
           const float* __restrict__ bhh, float* __restrict__ out) {
    __shared__ __half hsm[HH];           // staged h_{t-1}
    __shared__ float part[3 * 320];      // [gate][row(16), stride 20][warp(16)]

    const int tid = threadIdx.x;
    const int w   = tid >> 5;
    const int l   = tid & 31;
    const int gid = l >> 2;
    const int tig = l & 3;
    const int j0  = blockIdx.x * 16;
    const int kbase = w * 128;

    // ---- one-time: W_hh A-fragments into registers (96 regs) ----
    unsigned wa[48][2];
#pragma unroll
    for (int g = 0; g < 3; ++g) {
#pragma unroll
        for (int kt = 0; kt < 16; ++kt) {
            const size_t r0 = (size_t)(g * HH + j0 + gid) * HH;
            const int c = kbase + kt * 8 + 2 * tig;
            float2 f0 = *(const float2*)(Whh + r0 + c);
            float2 f1 = *(const float2*)(Whh + r0 + (size_t)8 * HH + c);
            __half2 p0 = __floats2half2_rn(f0.x, f0.y);
            __half2 p1 = __floats2half2_rn(f1.x, f1.y);
            wa[g * 16 + kt][0] = *reinterpret_cast<unsigned*>(&p0);
            wa[g * 16 + kt][1] = *reinterpret_cast<unsigned*>(&p1);
        }
    }

    // combined biases (threads 0-15)
    const int j = j0 + tid;
    float brc = 0.f, bzc = 0.f, bnn = 0.f, cnn = 0.f;
    if (tid < 16) {
        brc = bih[j] + bhh[j];
        bzc = bih[HH + j] + bhh[HH + j];
        cnn = bih[2 * HH + j];
        bnn = bhh[2 * HH + j];
    }

    float hown = 0.f;

#pragma unroll 1
    for (int t = 0; t < SQ; ++t) {
        // xi prefetch (hidden behind barrier + MMA)
        float xr = 0.f, xz = 0.f, xn = 0.f;
        if (tid < 16) {
            const float* xt = g_xi + (size_t)t * H3 + j;
            xr = __ldcg(xt);
            xz = __ldcg(xt + HH);
            xn = __ldcg(xt + 2 * HH);
        }

        if (t > 0) {
            // ---- acquire: wait for all blocks to finish step t-1 (R3-proven) ----
            if (tid == 0) {
                const unsigned target = (unsigned)t * NB;
                while (*(volatile unsigned*)&g_sync < target) {}
                __threadfence();
            }
            __syncthreads();
            // stage h_{t-1} into smem (L2-fresh loads)
            ((uint2*)hsm)[tid] = __ldcg(((const uint2*)g_h[(t - 1) & 1]) + tid);
            __syncthreads();

            // ---- GEMV via m16n8k8 HMMA: gate-major, 4 live accumulators ----
#pragma unroll
            for (int g = 0; g < 3; ++g) {
                float a0 = 0.f, a1 = 0.f, a2 = 0.f, a3 = 0.f;
#pragma unroll
                for (int kt = 0; kt < 16; ++kt) {
                    const unsigned b =
                        *(const unsigned*)(hsm + kbase + kt * 8 + 2 * tig);
                    asm volatile(
                        "mma.sync.aligned.m16n8k8.row.col.f32.f16.f16.f32 "
                        "{%0,%1,%2,%3}, {%4,%5}, {%6}, {%0,%1,%2,%3};"
                        : "+f"(a0), "+f"(a1), "+f"(a2), "+f"(a3)
                        : "r"(wa[g * 16 + kt][0]), "r"(wa[g * 16 + kt][1]),
                          "r"(b));
                }
                if (tig == 0) {
                    part[g * 320 + gid * 20 + w]       = a0;   // row gid, col 0
                    part[g * 320 + (gid + 8) * 20 + w] = a2;   // row gid+8, col 0
                }
            }
        }
        __syncthreads();

        if (tid < 16) {
            float s0 = 0.f, s1 = 0.f, s2 = 0.f;
            if (t > 0) {
                float s[3];
#pragma unroll
                for (int g = 0; g < 3; ++g) {
                    const float4* pp = (const float4*)(part + g * 320 + tid * 20);
                    float4 q0 = pp[0], q1 = pp[1], q2 = pp[2], q3 = pp[3];
                    s[g] = ((q0.x + q0.y) + (q0.z + q0.w)) +
                           ((q1.x + q1.y) + (q1.z + q1.w)) +
                           ((q2.x + q2.y) + (q2.z + q2.w)) +
                           ((q3.x + q3.y) + (q3.z + q3.w));
                }
                s0 = s[0]; s1 = s[1]; s2 = s[2];
            }
            const float rg = 1.f / (1.f + __expf(-(xr + s0 + brc)));
            const float zg = 1.f / (1.f + __expf(-(xz + s1 + bzc)));
            const float ng = tanhf(xn + cnn + rg * (s2 + bnn));
            hown = (1.f - zg) * ng + zg * hown;
            g_h[t & 1][j] = __float2half_rn(hown);
            __threadfence();   // release this thread's h store before the counter bump
        }
        __syncthreads();
        if (tid == 0) { __threadfence(); atomicAdd(&g_sync, 1u); }
    }

    if (tid < 16) out[j] = hown;
}

// -------- launcher --------
extern "C" void kernel_launch(void* const* d_in, const int* in_sizes, int n_in,
                              void* d_out, int out_size) {
    const float* x   = (const float*)d_in[0];
    const float* Wih = (const float*)d_in[1];
    const float* Whh = (const float*)d_in[2];
    const float* bih = (const float*)d_in[3];
    const float* bhh = (const float*)d_in[4];
    float* out = (float*)d_out;

    k_init<<<1, 1>>>();
    k_cvt_x<<<2048, 256>>>((const float2*)x);
    k_cvt_wih<<<2048, 256>>>((const float2*)Wih);

    const int gemm_smem = 2 * (BM + BN) * LDT * (int)sizeof(__half); // 49152
    cudaFuncSetAttribute(k_gemm, cudaFuncAttributeMaxDynamicSharedMemorySize, gemm_smem);
    dim3 ggrid(H3 / BN, SQ / BM);
    k_gemm<<<ggrid, 256, gemm_smem>>>();

    k_gru<<<NB, TPB>>>(Whh, bih, bhh, out);
}